// round 1
// baseline (speedup 1.0000x reference)
#include <cuda_runtime.h>

#define Vn 55
#define Cn 64
#define Dn 64
#define Tn 128
#define Nn 64
#define NTn (Nn * Tn)          // 8192
#define VD (Vn * Dn)           // 3520
#define VC (Vn * Cn)           // 3520
#define TOTAL (NTn * VD)       // 28,835,840

// Intermediate g in [n][t][d][v] layout (so temporal kernel reads contiguous v)
__device__ float g_buf[TOTAL];
// Precomputed fused parameters
__device__ float d_m[VC];      // tanh(feature_mask)+1, [v*C+c]
__device__ float d_A1[VD];     // BN1 scale, [u*D+d]
__device__ float d_B1[VD];     // BN1 shift with conv bias folded
__device__ float d_A2[Dn];     // BN2 scale
__device__ float d_B2[Dn];     // BN2 shift

typedef unsigned long long u64t;

__device__ __forceinline__ u64t pack_dup(float v) {
    u64t r; unsigned ui = __float_as_uint(v);
    asm("mov.b64 %0, {%1, %1};" : "=l"(r) : "r"(ui));
    return r;
}
__device__ __forceinline__ u64t pack2(float lo, float hi) {
    u64t r;
    asm("mov.b64 %0, {%1, %2};" : "=l"(r) : "r"(__float_as_uint(lo)), "r"(__float_as_uint(hi)));
    return r;
}
__device__ __forceinline__ void fma2(u64t& acc, u64t a, u64t b) {
    asm("fma.rn.f32x2 %0, %1, %2, %0;" : "+l"(acc) : "l"(a), "l"(b));
}
__device__ __forceinline__ void unpack2(u64t v, float& lo, float& hi) {
    asm("mov.b64 {%0, %1}, %2;" : "=f"(lo), "=f"(hi) : "l"(v));
}

__global__ __launch_bounds__(256) void prep_kernel(
    const float* __restrict__ fm, const float* __restrict__ b,
    const float* __restrict__ g1, const float* __restrict__ be1,
    const float* __restrict__ m1, const float* __restrict__ v1,
    const float* __restrict__ g2, const float* __restrict__ be2,
    const float* __restrict__ m2, const float* __restrict__ v2)
{
    int i = blockIdx.x * 256 + threadIdx.x;
    if (i < VC) d_m[i] = tanhf(fm[i]) + 1.0f;
    if (i < VD) {
        float a = g1[i] * rsqrtf(v1[i] + 1e-5f);
        d_A1[i] = a;
        d_B1[i] = be1[i] + a * (b[i & 63] - m1[i]);
    }
    if (i < Dn) {
        float a = g2[i] * rsqrtf(v2[i] + 1e-5f);
        d_A2[i] = a;
        d_B2[i] = be2[i] - a * m2[i];
    }
}

// One block per (n, t). Spatial shift + mask + 55x64x64 GEMM + BN1 + inverse shift + ReLU.
__global__ __launch_bounds__(256) void kernelA(const float* __restrict__ x,
                                               const float* __restrict__ W)
{
    __shared__ __align__(16) float xs[Cn * 56];   // xs[c*56+v]; later reused as gs[d*55+vv]
    __shared__ __align__(16) float hsT[Cn * 56];  // hsT[c*56+u] (u-contiguous)
    __shared__ __align__(16) float ws[Cn * Dn];   // W row-major

    const int tid = threadIdx.x;
    const int nt = blockIdx.x;
    const int n = nt >> 7;
    const int t = nt & 127;

    // Load x slab: x[n][c][t][v] -> xs[c][v]
    for (int i = tid; i < Cn * Vn; i += 256) {
        int c = i / Vn;
        int v = i - c * Vn;
        xs[c * 56 + v] = x[(((size_t)n * Cn + c) * Tn + t) * Vn + v];
    }
    for (int i = tid; i < Cn * Dn; i += 256) ws[i] = W[i];
    __syncthreads();

    // hsT[c][u] = xs[c][(u+c)%V] * m[u][c]   (pad u=55 with 0)
    for (int i = tid; i < Cn * 56; i += 256) {
        int c = i / 56;
        int u = i - c * 56;
        float val = 0.0f;
        if (u < Vn) {
            int s = u + c;
            if (s >= Vn) s -= Vn;
            if (s >= Vn) s -= Vn;
            val = xs[c * 56 + s] * d_m[u * Cn + c];
        }
        hsT[i] = val;
    }
    __syncthreads();

    // GEMM: y[u][d] = sum_c hsT[c][u] * ws[c][d]
    // Thread tile: 4 u (contiguous) x 4 d (contiguous). dg in [0,16), ut in [0,14).
    const int dg = tid & 15;
    const int ut = tid >> 4;

    u64t acc[4][2];
#pragma unroll
    for (int a = 0; a < 4; a++) { acc[a][0] = 0ull; acc[a][1] = 0ull; }

    if (ut < 14) {
        for (int c0 = 0; c0 < Cn; c0 += 8) {
            u64t wreg[8][2];
#pragma unroll
            for (int i = 0; i < 8; i++) {
                float4 w4 = *reinterpret_cast<const float4*>(&ws[(c0 + i) * Dn + dg * 4]);
                wreg[i][0] = pack2(w4.x, w4.y);
                wreg[i][1] = pack2(w4.z, w4.w);
            }
#pragma unroll
            for (int i = 0; i < 8; i++) {
                float4 h4 = *reinterpret_cast<const float4*>(&hsT[(c0 + i) * 56 + ut * 4]);
                u64t h;
                h = pack_dup(h4.x); fma2(acc[0][0], h, wreg[i][0]); fma2(acc[0][1], h, wreg[i][1]);
                h = pack_dup(h4.y); fma2(acc[1][0], h, wreg[i][0]); fma2(acc[1][1], h, wreg[i][1]);
                h = pack_dup(h4.z); fma2(acc[2][0], h, wreg[i][0]); fma2(acc[2][1], h, wreg[i][1]);
                h = pack_dup(h4.w); fma2(acc[3][0], h, wreg[i][0]); fma2(acc[3][1], h, wreg[i][1]);
            }
        }

        // Epilogue: BN1 + ReLU, inverse shift to gs[d][ (u+d)%V ], staged in xs
#pragma unroll
        for (int uu = 0; uu < 4; uu++) {
            int u = ut * 4 + uu;
            if (u >= Vn) break;
#pragma unroll
            for (int jj = 0; jj < 2; jj++) {
                float lo, hi;
                unpack2(acc[uu][jj], lo, hi);
                int d0 = dg * 4 + jj * 2;
                int idx0 = u * Dn + d0;
                float y0 = fmaxf(d_A1[idx0] * lo + d_B1[idx0], 0.0f);
                float y1 = fmaxf(d_A1[idx0 + 1] * hi + d_B1[idx0 + 1], 0.0f);
                int s0 = u + d0;
                if (s0 >= Vn) s0 -= Vn;
                if (s0 >= Vn) s0 -= Vn;
                int s1 = s0 + 1;
                if (s1 >= Vn) s1 -= Vn;
                xs[d0 * Vn + s0] = y0;
                xs[(d0 + 1) * Vn + s1] = y1;
            }
        }
    }
    __syncthreads();

    // Coalesced store of g[n][t][d][v]
    const size_t base = (size_t)nt * VD;
    for (int i = tid; i < VD; i += 256) g_buf[base + i] = xs[i];
}

// Elementwise: temporal shift + BN2 + residual + ReLU. Fully coalesced.
__global__ __launch_bounds__(256) void kernelB(const float* __restrict__ x,
                                               float* __restrict__ out)
{
    int idx = blockIdx.x * 256 + threadIdx.x;   // < 28,835,840
    int v = idx % Vn;
    int r = idx / Vn;       // (n*64+c)*128 + t
    int t = r & 127;
    int nc = r >> 7;        // n*64+c
    int c = nc & 63;
    int off = (c % 3) - 1;
    int tt = t + off;
    float gval = 0.0f;
    if ((unsigned)tt < (unsigned)Tn) {
        int n = nc >> 6;
        gval = g_buf[(((size_t)n * Tn + tt) * Dn + c) * Vn + v];
    }
    float res = d_A2[c] * gval + d_B2[c] + x[idx];
    out[idx] = fmaxf(res, 0.0f);
}

extern "C" void kernel_launch(void* const* d_in, const int* in_sizes, int n_in,
                              void* d_out, int out_size)
{
    const float* x   = (const float*)d_in[0];
    const float* W   = (const float*)d_in[1];
    const float* b   = (const float*)d_in[2];
    const float* fm  = (const float*)d_in[3];
    const float* g1  = (const float*)d_in[4];
    const float* be1 = (const float*)d_in[5];
    const float* m1  = (const float*)d_in[6];
    const float* v1  = (const float*)d_in[7];
    const float* g2  = (const float*)d_in[8];
    const float* be2 = (const float*)d_in[9];
    const float* m2  = (const float*)d_in[10];
    const float* v2  = (const float*)d_in[11];
    float* out = (float*)d_out;

    prep_kernel<<<14, 256>>>(fm, b, g1, be1, m1, v1, g2, be2, m2, v2);
    kernelA<<<NTn, 256>>>(x, W);
    kernelB<<<TOTAL / 256, 256>>>(x, out);
}